// round 11
// baseline (speedup 1.0000x reference)
#include <cuda_runtime.h>
#include <math.h>

// Problem constants
#define BB   4
#define CC_  64
#define HWK  1024
#define TT   32
#define NHK  8
#define SSK  512
#define COLS 32768       // HW*T
#define QKVO 192         // 3*C

#define SCALE_LOGIT 0.011048543456039806f   // 1/sqrt(8192)

// Packed fp32x2 helpers (Blackwell dual-fp32 pipe)
#define FFMA2(d, a, b, c) \
    asm("fma.rn.f32x2 %0, %1, %2, %3;" : "=l"(d) : "l"(a), "l"(b), "l"(c))
#define PACK2(d, x) \
    asm("mov.b64 %0, {%1, %1};" : "=l"(d) : "r"(__float_as_uint(x)))
#define UNPACK2(lo, hi, v) \
    asm("mov.b64 {%0, %1}, %2;" : "=r"(lo), "=r"(hi) : "l"(v))

typedef unsigned long long u64t;

// Scratch (static __device__ allocations — allowed)
__device__ __align__(16) float g_wqkv[BB * QKVO * CC_];          // [b][o][c]
__device__ __align__(16) float g_wproj[BB * CC_ * CC_];          // [b][o][c]
__device__ __align__(16) float g_qkv[BB * QKVO * COLS];          // [b][o][col]
__device__ __align__(16) float g_tmp[BB * CC_ * COLS];           // attn@V result
__device__ __align__(16) float g_lpart[BB * NHK * 8 * TT * TT];  // logit partials
__device__ __align__(16) float g_attn[BB * NHK * TT * TT];       // softmaxed attn

// ---------------------------------------------------------------------------
// K1: style projection + modulated/demodulated weights.  grid=(B), 256 thr
// ---------------------------------------------------------------------------
__global__ void k1_weights(const float* __restrict__ style,
                           const float* __restrict__ qkv_w,
                           const float* __restrict__ qkv_lw,
                           const float* __restrict__ qkv_lb,
                           const float* __restrict__ proj_w,
                           const float* __restrict__ proj_lw,
                           const float* __restrict__ proj_lb) {
    __shared__ __align__(16) float st[SSK];
    __shared__ float sq[CC_];
    __shared__ float sp[CC_];
    int b = blockIdx.x, tid = threadIdx.x;
    st[tid]       = style[b * SSK + tid];
    st[tid + 256] = style[b * SSK + tid + 256];
    __syncthreads();

    if (tid < 128) {
        int c = tid & 63;
        const float* lw = ((tid < 64) ? qkv_lw : proj_lw) + c * SSK;
        float acc = 0.f;
        #pragma unroll 4
        for (int k = 0; k < SSK; k += 4) {
            float4 a  = *(const float4*)(lw + k);
            float4 s4 = *(const float4*)(st + k);
            acc += a.x * s4.x + a.y * s4.y + a.z * s4.z + a.w * s4.w;
        }
        if (tid < 64) sq[c] = acc + qkv_lb[c];
        else          sp[c] = acc + proj_lb[c];
    }
    __syncthreads();

    if (tid < QKVO) {
        int o = tid;
        const float* wr = qkv_w + o * CC_;
        float ss = 0.f;
        #pragma unroll 8
        for (int c = 0; c < CC_; c++) { float v = wr[c] * sq[c]; ss += v * v; }
        float si = rsqrtf(ss + 1e-8f);
        float* dst = g_wqkv + (b * QKVO + o) * CC_;
        #pragma unroll 8
        for (int c = 0; c < CC_; c++) dst[c] = wr[c] * sq[c] * si;
    } else {
        int o = tid - QKVO;
        const float* wr = proj_w + o * CC_;
        float ss = 0.f;
        #pragma unroll 8
        for (int c = 0; c < CC_; c++) { float v = wr[c] * sp[c]; ss += v * v; }
        float si = rsqrtf(ss + 1e-8f);
        float* dst = g_wproj + (b * CC_ + o) * CC_;
        #pragma unroll 8
        for (int c = 0; c < CC_; c++) dst[c] = wr[c] * sp[c] * si;
    }
}

// ---------------------------------------------------------------------------
// K2: qkv = W(192x64) @ X(64x32768) per batch + noise/bias epilogue.
// grid=(256, B), 256 thr. One block computes ALL 192 outputs for its 128-col
// tile (X read once from DRAM, not 3x).  smem: X 32KB + W 48KB = 80KB.
// f32x2 micro-kernel: 4 o x 8 cols per thread, cols {tx*4..+3} u {64+tx*4..+3}.
// ---------------------------------------------------------------------------
__global__ __launch_bounds__(256) void k2_qkv(
        const float* __restrict__ x,
        const float* __restrict__ qkv_np,
        const float* __restrict__ qkv_bp,
        const float* __restrict__ qkv_noise) {
    extern __shared__ float smem[];
    float* sX = smem;            // [64][128]
    float* sW = smem + 64 * 128; // [ot][c][o]  3 x 64 x 64

    int b = blockIdx.y, nb = blockIdx.x;
    int tid = threadIdx.x;
    int colBase = nb * 128;

    const float4* xs = (const float4*)(x + (size_t)b * (CC_ * COLS) + colBase);
    #pragma unroll
    for (int i = 0; i < 8; i++) {
        int fidx = tid + i * 256;
        int r = fidx >> 5, c4 = fidx & 31;
        ((float4*)sX)[r * 32 + c4] = xs[r * (COLS / 4) + c4];
    }
    const float* gw = g_wqkv + (size_t)b * QKVO * CC_;
    #pragma unroll
    for (int i = 0; i < 48; i++) {
        int fidx = tid + i * 256;            // 0..12287
        int o = fidx >> 6, c = fidx & 63;
        sW[(o >> 6) * 4096 + c * 64 + (o & 63)] = gw[o * CC_ + c];
    }
    __syncthreads();

    int tx = tid & 15, ty = tid >> 4;
    int colA = colBase + tx * 4;
    int colB = colA + 64;
    float4 nzA = *(const float4*)(qkv_noise + (size_t)b * COLS + colA);
    float4 nzB = *(const float4*)(qkv_noise + (size_t)b * COLS + colB);

    #pragma unroll
    for (int ot = 0; ot < 3; ot++) {
        const float* sWb = sW + ot * 4096;
        u64t acc2[4][4];
        #pragma unroll
        for (int oi = 0; oi < 4; oi++)
            #pragma unroll
            for (int p = 0; p < 4; p++) acc2[oi][p] = 0ull;

        #pragma unroll 8
        for (int c = 0; c < 64; c++) {
            float4 w4 = *(const float4*)(sWb + c * 64 + ty * 4);
            u64t wp[4];
            PACK2(wp[0], w4.x); PACK2(wp[1], w4.y);
            PACK2(wp[2], w4.z); PACK2(wp[3], w4.w);
            ulonglong2 xa = *(const ulonglong2*)(sX + c * 128 + tx * 4);
            ulonglong2 xb = *(const ulonglong2*)(sX + c * 128 + 64 + tx * 4);
            #pragma unroll
            for (int oi = 0; oi < 4; oi++) {
                FFMA2(acc2[oi][0], wp[oi], xa.x, acc2[oi][0]);
                FFMA2(acc2[oi][1], wp[oi], xa.y, acc2[oi][1]);
                FFMA2(acc2[oi][2], wp[oi], xb.x, acc2[oi][2]);
                FFMA2(acc2[oi][3], wp[oi], xb.y, acc2[oi][3]);
            }
        }

        #pragma unroll
        for (int oi = 0; oi < 4; oi++) {
            int o = ot * 64 + ty * 4 + oi;
            float npc = qkv_np[o], bpc = qkv_bp[o];
            unsigned r0, r1, r2, r3;
            float* dst = g_qkv + (size_t)(b * QKVO + o) * COLS;
            UNPACK2(r0, r1, acc2[oi][0]);
            UNPACK2(r2, r3, acc2[oi][1]);
            *(float4*)(dst + colA) = make_float4(
                __uint_as_float(r0) + npc * nzA.x + bpc,
                __uint_as_float(r1) + npc * nzA.y + bpc,
                __uint_as_float(r2) + npc * nzA.z + bpc,
                __uint_as_float(r3) + npc * nzA.w + bpc);
            UNPACK2(r0, r1, acc2[oi][2]);
            UNPACK2(r2, r3, acc2[oi][3]);
            *(float4*)(dst + colB) = make_float4(
                __uint_as_float(r0) + npc * nzB.x + bpc,
                __uint_as_float(r1) + npc * nzB.y + bpc,
                __uint_as_float(r2) + npc * nzB.z + bpc,
                __uint_as_float(r3) + npc * nzB.w + bpc);
        }
    }
}

// ---------------------------------------------------------------------------
// K3a: attention logit partials, f32x2 along j.  grid=(8,NH,B), 256 thr.
// ---------------------------------------------------------------------------
__global__ void k3a_logits() {
    __shared__ __align__(16) float qS[128 * 32];
    __shared__ __align__(16) float kS[128 * 32];
    __shared__ __align__(16) float red[4 * 1024];
    int s = blockIdx.x, n = blockIdx.y, b = blockIdx.z;
    int tid = threadIdx.x;
    int g = tid >> 6, gt = tid & 63;
    int i0 = (gt >> 3) * 4, j0 = (gt & 7) * 4;
    int p0 = g * 32;

    u64t acc2[4][2];
    #pragma unroll
    for (int a = 0; a < 4; a++) { acc2[a][0] = 0ull; acc2[a][1] = 0ull; }

    for (int cc = 0; cc < 8; cc++) {
        const float4* q4 = (const float4*)(g_qkv + (size_t)(b * QKVO + n * 8 + cc) * COLS + s * 128 * TT);
        const float4* k4 = q4 + 64 * (COLS / 4);   // k channels are +64
        #pragma unroll
        for (int r = 0; r < 4; r++) {
            ((float4*)qS)[tid + r * 256] = q4[tid + r * 256];
            ((float4*)kS)[tid + r * 256] = k4[tid + r * 256];
        }
        __syncthreads();
        #pragma unroll 4
        for (int p = p0; p < p0 + 32; p++) {
            float4 qv = *(const float4*)(qS + p * 32 + i0);
            ulonglong2 kv = *(const ulonglong2*)(kS + p * 32 + j0);
            u64t qp[4];
            PACK2(qp[0], qv.x); PACK2(qp[1], qv.y);
            PACK2(qp[2], qv.z); PACK2(qp[3], qv.w);
            #pragma unroll
            for (int a = 0; a < 4; a++) {
                FFMA2(acc2[a][0], qp[a], kv.x, acc2[a][0]);
                FFMA2(acc2[a][1], qp[a], kv.y, acc2[a][1]);
            }
        }
        __syncthreads();
    }

    #pragma unroll
    for (int a = 0; a < 4; a++) {
        unsigned v0, v1, v2, v3;
        UNPACK2(v0, v1, acc2[a][0]);
        UNPACK2(v2, v3, acc2[a][1]);
        *(float4*)(red + g * 1024 + (i0 + a) * 32 + j0) =
            make_float4(__uint_as_float(v0), __uint_as_float(v1),
                        __uint_as_float(v2), __uint_as_float(v3));
    }
    __syncthreads();

    float4 r0 = ((const float4*)(red))[tid];
    float4 r1 = ((const float4*)(red + 1024))[tid];
    float4 r2 = ((const float4*)(red + 2048))[tid];
    float4 r3 = ((const float4*)(red + 3072))[tid];
    float4 o = make_float4(r0.x + r1.x + r2.x + r3.x,
                           r0.y + r1.y + r2.y + r3.y,
                           r0.z + r1.z + r2.z + r3.z,
                           r0.w + r1.w + r2.w + r3.w);
    float* dst = g_lpart + (size_t)((b * NHK + n) * 8 + s) * 1024;
    ((float4*)dst)[tid] = o;
}

// ---------------------------------------------------------------------------
// K3b: reduce partials + scale + ALiBi + mask + softmax. grid=(NH,B), 1024thr.
// ---------------------------------------------------------------------------
__global__ void k3b_softmax() {
    int n = blockIdx.x, b = blockIdx.y;
    int tid = threadIdx.x;
    int i = tid >> 5, j = tid & 31;
    float slope = exp2f(-(float)(n + 1));
    const float* src = g_lpart + (size_t)(b * NHK + n) * 8 * TT * TT + i * 32 + j;
    float v = 0.f;
    #pragma unroll
    for (int s = 0; s < 8; s++) v += src[s * 1024];
    v = v * SCALE_LOGIT + slope * (-fabsf((float)(i - j)));
    if (j <= i) v = -1e18f;   // faithful: lower triangle masked
    float mx = v;
    #pragma unroll
    for (int d = 16; d > 0; d >>= 1) mx = fmaxf(mx, __shfl_xor_sync(0xffffffffu, mx, d));
    float e = expf(v - mx);
    float sum = e;
    #pragma unroll
    for (int d = 16; d > 0; d >>= 1) sum += __shfl_xor_sync(0xffffffffu, sum, d);
    g_attn[(size_t)(b * NHK + n) * TT * TT + i * 32 + j] = e / sum;
}

// ---------------------------------------------------------------------------
// K4a: tmp[c, hw, t] = sum_j v[c, hw, j] * attn[n(c)][t][j]
// grid=(8 hwTiles, 64 c, B), 256 thr.
// ---------------------------------------------------------------------------
#define APS 34
__global__ void k4a_av() {
    __shared__ __align__(16) float attnS[TT * APS];    // [t][j]
    __shared__ __align__(16) float sV[128 * APS];      // [hw][j]

    int hwt = blockIdx.x, c = blockIdx.y, b = blockIdx.z;
    int n = c >> 3;
    int tid = threadIdx.x;

    {
        const float* a = g_attn + (size_t)(b * NHK + n) * TT * TT;
        #pragma unroll
        for (int k = 0; k < 4; k++) {
            int idx = tid + k * 256;
            attnS[(idx >> 5) * APS + (idx & 31)] = a[idx];
        }
    }
    {
        const ulonglong2* v2 = (const ulonglong2*)(g_qkv + ((size_t)(b * QKVO + 128 + c) * COLS) + hwt * 128 * TT);
        u64t* sVu = (u64t*)sV;
        #pragma unroll
        for (int k = 0; k < 4; k++) {
            int idx = tid + k * 256;
            int hw = idx >> 3, j4 = idx & 7;
            ulonglong2 val = v2[idx];
            sVu[hw * (APS / 2) + j4 * 2]     = val.x;
            sVu[hw * (APS / 2) + j4 * 2 + 1] = val.y;
        }
    }
    __syncthreads();

    int tx = tid & 31, ty = tid >> 5;
    int t0 = ty * 4;
    const u64t* aU = (const u64t*)attnS;
    const u64t* vU = (const u64t*)sV;

    u64t acc2[4][4];
    #pragma unroll
    for (int i = 0; i < 4; i++)
        #pragma unroll
        for (int t = 0; t < 4; t++) acc2[i][t] = 0ull;

    #pragma unroll 8
    for (int j2 = 0; j2 < 16; j2++) {
        u64t av[4], vv[4];
        #pragma unroll
        for (int t = 0; t < 4; t++) av[t] = aU[(t0 + t) * (APS / 2) + j2];
        #pragma unroll
        for (int i = 0; i < 4; i++) vv[i] = vU[(tx + 32 * i) * (APS / 2) + j2];
        #pragma unroll
        for (int i = 0; i < 4; i++)
            #pragma unroll
            for (int t = 0; t < 4; t++)
                FFMA2(acc2[i][t], vv[i], av[t], acc2[i][t]);
    }

    float* dst = g_tmp + (size_t)(b * CC_ + c) * COLS + hwt * 128 * TT;
    #pragma unroll
    for (int i = 0; i < 4; i++) {
        float r[4];
        #pragma unroll
        for (int t = 0; t < 4; t++) {
            unsigned lo, hi;
            UNPACK2(lo, hi, acc2[i][t]);
            r[t] = __uint_as_float(lo) + __uint_as_float(hi);
        }
        *(float4*)(dst + (tx + 32 * i) * TT + t0) = make_float4(r[0], r[1], r[2], r[3]);
    }
}

// ---------------------------------------------------------------------------
// K4b: out = Wp(64x64) @ tmp(64x32768) per batch + proj noise/bias.
// grid=(256,1,B), 256 thr.
// ---------------------------------------------------------------------------
__global__ void k4b_proj(const float* __restrict__ proj_np,
                         const float* __restrict__ proj_bp,
                         const float* __restrict__ proj_noise,
                         float* __restrict__ out) {
    extern __shared__ float smem[];
    float* sX = smem;            // [64][128]
    float* sW = smem + 64 * 128; // [c][o]

    int b = blockIdx.z, nb = blockIdx.x;
    int tid = threadIdx.x;
    int colBase = nb * 128;

    const float4* xs = (const float4*)(g_tmp + (size_t)b * (CC_ * COLS) + colBase);
    #pragma unroll
    for (int i = 0; i < 8; i++) {
        int fidx = tid + i * 256;
        int r = fidx >> 5, c4 = fidx & 31;
        ((float4*)sX)[r * 32 + c4] = xs[r * (COLS / 4) + c4];
    }
    const float* gw = g_wproj + b * CC_ * CC_;
    #pragma unroll
    for (int i = 0; i < 16; i++) {
        int fidx = tid + i * 256;
        int ol = fidx >> 6, c = fidx & 63;
        sW[c * 64 + ol] = gw[ol * CC_ + c];
    }
    __syncthreads();

    int tx = tid & 15, ty = tid >> 4;
    u64t acc2[4][4];
    #pragma unroll
    for (int oi = 0; oi < 4; oi++)
        #pragma unroll
        for (int p = 0; p < 4; p++) acc2[oi][p] = 0ull;

    #pragma unroll 8
    for (int c = 0; c < 64; c++) {
        float4 w4 = *(const float4*)(sW + c * 64 + ty * 4);
        u64t wp[4];
        PACK2(wp[0], w4.x); PACK2(wp[1], w4.y);
        PACK2(wp[2], w4.z); PACK2(wp[3], w4.w);
        ulonglong2 xa = *(const ulonglong2*)(sX + c * 128 + tx * 4);
        ulonglong2 xb = *(const ulonglong2*)(sX + c * 128 + 64 + tx * 4);
        #pragma unroll
        for (int oi = 0; oi < 4; oi++) {
            FFMA2(acc2[oi][0], wp[oi], xa.x, acc2[oi][0]);
            FFMA2(acc2[oi][1], wp[oi], xa.y, acc2[oi][1]);
            FFMA2(acc2[oi][2], wp[oi], xb.x, acc2[oi][2]);
            FFMA2(acc2[oi][3], wp[oi], xb.y, acc2[oi][3]);
        }
    }

    int colA = colBase + tx * 4;
    int colB = colA + 64;
    float4 nzA = *(const float4*)(proj_noise + b * COLS + colA);
    float4 nzB = *(const float4*)(proj_noise + b * COLS + colB);
    #pragma unroll
    for (int oi = 0; oi < 4; oi++) {
        int o = ty * 4 + oi;
        float npc = proj_np[o], bpc = proj_bp[o];
        unsigned r0, r1, r2, r3;
        float* dst = out + (size_t)(b * CC_ + o) * COLS;
        UNPACK2(r0, r1, acc2[oi][0]);
        UNPACK2(r2, r3, acc2[oi][1]);
        *(float4*)(dst + colA) = make_float4(
            __uint_as_float(r0) + npc * nzA.x + bpc,
            __uint_as_float(r1) + npc * nzA.y + bpc,
            __uint_as_float(r2) + npc * nzA.z + bpc,
            __uint_as_float(r3) + npc * nzA.w + bpc);
        UNPACK2(r0, r1, acc2[oi][2]);
        UNPACK2(r2, r3, acc2[oi][3]);
        *(float4*)(dst + colB) = make_float4(
            __uint_as_float(r0) + npc * nzB.x + bpc,
            __uint_as_float(r1) + npc * nzB.y + bpc,
            __uint_as_float(r2) + npc * nzB.z + bpc,
            __uint_as_float(r3) + npc * nzB.w + bpc);
    }
}

// ---------------------------------------------------------------------------
extern "C" void kernel_launch(void* const* d_in, const int* in_sizes, int n_in,
                              void* d_out, int out_size) {
    const float* x          = (const float*)d_in[0];
    const float* style      = (const float*)d_in[1];
    const float* qkv_w      = (const float*)d_in[2];
    const float* qkv_lw     = (const float*)d_in[3];
    const float* qkv_lb     = (const float*)d_in[4];
    const float* qkv_np     = (const float*)d_in[5];
    const float* qkv_bp     = (const float*)d_in[6];
    const float* qkv_noise  = (const float*)d_in[7];
    const float* proj_w     = (const float*)d_in[8];
    const float* proj_lw    = (const float*)d_in[9];
    const float* proj_lb    = (const float*)d_in[10];
    const float* proj_np    = (const float*)d_in[11];
    const float* proj_bp    = (const float*)d_in[12];
    const float* proj_noise = (const float*)d_in[13];
    float* out = (float*)d_out;

    const int smem_k2   = (64 * 128 + 3 * 64 * 64) * 4;   // 81920
    const int smem_gemm = (64 * 128 + 64 * 64) * 4;       // 49152
    cudaFuncSetAttribute(k2_qkv,   cudaFuncAttributeMaxDynamicSharedMemorySize, smem_k2);
    cudaFuncSetAttribute(k4b_proj, cudaFuncAttributeMaxDynamicSharedMemorySize, smem_gemm);

    k1_weights<<<BB, 256>>>(style, qkv_w, qkv_lw, qkv_lb, proj_w, proj_lw, proj_lb);
    k2_qkv<<<dim3(256, BB), 256, smem_k2>>>(x, qkv_np, qkv_bp, qkv_noise);
    k3a_logits<<<dim3(8, NHK, BB), 256>>>();
    k3b_softmax<<<dim3(NHK, BB), 1024>>>();
    k4a_av<<<dim3(8, CC_, BB), 256>>>();
    k4b_proj<<<dim3(256, 1, BB), 256, smem_gemm>>>(proj_np, proj_bp, proj_noise, out);
}

// round 12
// speedup vs baseline: 1.0046x; 1.0046x over previous
#include <cuda_runtime.h>
#include <math.h>

// Problem constants
#define BB   4
#define CC_  64
#define HWK  1024
#define TT   32
#define NHK  8
#define SSK  512
#define COLS 32768       // HW*T
#define QKVO 192         // 3*C

#define SCALE_LOGIT 0.011048543456039806f   // 1/sqrt(8192)

// Packed fp32x2 helpers (Blackwell dual-fp32 pipe)
#define FFMA2(d, a, b, c) \
    asm("fma.rn.f32x2 %0, %1, %2, %3;" : "=l"(d) : "l"(a), "l"(b), "l"(c))
#define PACK2(d, x) \
    asm("mov.b64 %0, {%1, %1};" : "=l"(d) : "r"(__float_as_uint(x)))
#define UNPACK2(lo, hi, v) \
    asm("mov.b64 {%0, %1}, %2;" : "=r"(lo), "=r"(hi) : "l"(v))

typedef unsigned long long u64t;

// Scratch (static __device__ allocations — allowed)
__device__ __align__(16) float g_wqkv[BB * QKVO * CC_];          // [b][o][c]
__device__ __align__(16) float g_wproj[BB * CC_ * CC_];          // [b][o][c]
__device__ __align__(16) float g_qkv[BB * QKVO * COLS];          // [b][o][col]
__device__ __align__(16) float g_tmp[BB * CC_ * COLS];           // attn@V result
__device__ __align__(16) float g_lpart[BB * NHK * 8 * TT * TT];  // logit partials
__device__ __align__(16) float g_attn[BB * NHK * TT * TT];       // softmaxed attn

// ---------------------------------------------------------------------------
// K1: style projection + modulated/demodulated weights.  grid=(B), 256 thr
// ---------------------------------------------------------------------------
__global__ void k1_weights(const float* __restrict__ style,
                           const float* __restrict__ qkv_w,
                           const float* __restrict__ qkv_lw,
                           const float* __restrict__ qkv_lb,
                           const float* __restrict__ proj_w,
                           const float* __restrict__ proj_lw,
                           const float* __restrict__ proj_lb) {
    __shared__ __align__(16) float st[SSK];
    __shared__ float sq[CC_];
    __shared__ float sp[CC_];
    int b = blockIdx.x, tid = threadIdx.x;
    st[tid]       = style[b * SSK + tid];
    st[tid + 256] = style[b * SSK + tid + 256];
    __syncthreads();

    if (tid < 128) {
        int c = tid & 63;
        const float* lw = ((tid < 64) ? qkv_lw : proj_lw) + c * SSK;
        float acc = 0.f;
        #pragma unroll 4
        for (int k = 0; k < SSK; k += 4) {
            float4 a  = *(const float4*)(lw + k);
            float4 s4 = *(const float4*)(st + k);
            acc += a.x * s4.x + a.y * s4.y + a.z * s4.z + a.w * s4.w;
        }
        if (tid < 64) sq[c] = acc + qkv_lb[c];
        else          sp[c] = acc + proj_lb[c];
    }
    __syncthreads();

    if (tid < QKVO) {
        int o = tid;
        const float* wr = qkv_w + o * CC_;
        float ss = 0.f;
        #pragma unroll 8
        for (int c = 0; c < CC_; c++) { float v = wr[c] * sq[c]; ss += v * v; }
        float si = rsqrtf(ss + 1e-8f);
        float* dst = g_wqkv + (b * QKVO + o) * CC_;
        #pragma unroll 8
        for (int c = 0; c < CC_; c++) dst[c] = wr[c] * sq[c] * si;
    } else {
        int o = tid - QKVO;
        const float* wr = proj_w + o * CC_;
        float ss = 0.f;
        #pragma unroll 8
        for (int c = 0; c < CC_; c++) { float v = wr[c] * sp[c]; ss += v * v; }
        float si = rsqrtf(ss + 1e-8f);
        float* dst = g_wproj + (b * CC_ + o) * CC_;
        #pragma unroll 8
        for (int c = 0; c < CC_; c++) dst[c] = wr[c] * sp[c] * si;
    }
}

// ---------------------------------------------------------------------------
// K2: qkv = W(192x64) @ X(64x32768) per batch + noise/bias epilogue.
// grid=(256, B), 256 thr. One block computes ALL 192 outputs for its 128-col
// tile (X read once from DRAM, not 3x).  smem: X 32KB + W 48KB = 80KB.
// f32x2 micro-kernel: 4 o x 8 cols per thread, cols {tx*4..+3} u {64+tx*4..+3}.
// ---------------------------------------------------------------------------
__global__ __launch_bounds__(256) void k2_qkv(
        const float* __restrict__ x,
        const float* __restrict__ qkv_np,
        const float* __restrict__ qkv_bp,
        const float* __restrict__ qkv_noise) {
    extern __shared__ float smem[];
    float* sX = smem;            // [64][128]
    float* sW = smem + 64 * 128; // [ot][c][o]  3 x 64 x 64

    int b = blockIdx.y, nb = blockIdx.x;
    int tid = threadIdx.x;
    int colBase = nb * 128;

    const float4* xs = (const float4*)(x + (size_t)b * (CC_ * COLS) + colBase);
    #pragma unroll
    for (int i = 0; i < 8; i++) {
        int fidx = tid + i * 256;
        int r = fidx >> 5, c4 = fidx & 31;
        ((float4*)sX)[r * 32 + c4] = xs[r * (COLS / 4) + c4];
    }
    const float* gw = g_wqkv + (size_t)b * QKVO * CC_;
    #pragma unroll
    for (int i = 0; i < 48; i++) {
        int fidx = tid + i * 256;            // 0..12287
        int o = fidx >> 6, c = fidx & 63;
        sW[(o >> 6) * 4096 + c * 64 + (o & 63)] = gw[o * CC_ + c];
    }
    __syncthreads();

    int tx = tid & 15, ty = tid >> 4;
    int colA = colBase + tx * 4;
    int colB = colA + 64;
    float4 nzA = *(const float4*)(qkv_noise + (size_t)b * COLS + colA);
    float4 nzB = *(const float4*)(qkv_noise + (size_t)b * COLS + colB);

    #pragma unroll
    for (int ot = 0; ot < 3; ot++) {
        const float* sWb = sW + ot * 4096;
        u64t acc2[4][4];
        #pragma unroll
        for (int oi = 0; oi < 4; oi++)
            #pragma unroll
            for (int p = 0; p < 4; p++) acc2[oi][p] = 0ull;

        #pragma unroll 8
        for (int c = 0; c < 64; c++) {
            float4 w4 = *(const float4*)(sWb + c * 64 + ty * 4);
            u64t wp[4];
            PACK2(wp[0], w4.x); PACK2(wp[1], w4.y);
            PACK2(wp[2], w4.z); PACK2(wp[3], w4.w);
            ulonglong2 xa = *(const ulonglong2*)(sX + c * 128 + tx * 4);
            ulonglong2 xb = *(const ulonglong2*)(sX + c * 128 + 64 + tx * 4);
            #pragma unroll
            for (int oi = 0; oi < 4; oi++) {
                FFMA2(acc2[oi][0], wp[oi], xa.x, acc2[oi][0]);
                FFMA2(acc2[oi][1], wp[oi], xa.y, acc2[oi][1]);
                FFMA2(acc2[oi][2], wp[oi], xb.x, acc2[oi][2]);
                FFMA2(acc2[oi][3], wp[oi], xb.y, acc2[oi][3]);
            }
        }

        #pragma unroll
        for (int oi = 0; oi < 4; oi++) {
            int o = ot * 64 + ty * 4 + oi;
            float npc = qkv_np[o], bpc = qkv_bp[o];
            unsigned r0, r1, r2, r3;
            float* dst = g_qkv + (size_t)(b * QKVO + o) * COLS;
            UNPACK2(r0, r1, acc2[oi][0]);
            UNPACK2(r2, r3, acc2[oi][1]);
            *(float4*)(dst + colA) = make_float4(
                __uint_as_float(r0) + npc * nzA.x + bpc,
                __uint_as_float(r1) + npc * nzA.y + bpc,
                __uint_as_float(r2) + npc * nzA.z + bpc,
                __uint_as_float(r3) + npc * nzA.w + bpc);
            UNPACK2(r0, r1, acc2[oi][2]);
            UNPACK2(r2, r3, acc2[oi][3]);
            *(float4*)(dst + colB) = make_float4(
                __uint_as_float(r0) + npc * nzB.x + bpc,
                __uint_as_float(r1) + npc * nzB.y + bpc,
                __uint_as_float(r2) + npc * nzB.z + bpc,
                __uint_as_float(r3) + npc * nzB.w + bpc);
        }
    }
}

// ---------------------------------------------------------------------------
// K3a: attention logit partials, f32x2 along j.  grid=(8,NH,B), 256 thr.
// ---------------------------------------------------------------------------
__global__ void k3a_logits() {
    __shared__ __align__(16) float qS[128 * 32];
    __shared__ __align__(16) float kS[128 * 32];
    __shared__ __align__(16) float red[4 * 1024];
    int s = blockIdx.x, n = blockIdx.y, b = blockIdx.z;
    int tid = threadIdx.x;
    int g = tid >> 6, gt = tid & 63;
    int i0 = (gt >> 3) * 4, j0 = (gt & 7) * 4;
    int p0 = g * 32;

    u64t acc2[4][2];
    #pragma unroll
    for (int a = 0; a < 4; a++) { acc2[a][0] = 0ull; acc2[a][1] = 0ull; }

    for (int cc = 0; cc < 8; cc++) {
        const float4* q4 = (const float4*)(g_qkv + (size_t)(b * QKVO + n * 8 + cc) * COLS + s * 128 * TT);
        const float4* k4 = q4 + 64 * (COLS / 4);   // k channels are +64
        #pragma unroll
        for (int r = 0; r < 4; r++) {
            ((float4*)qS)[tid + r * 256] = q4[tid + r * 256];
            ((float4*)kS)[tid + r * 256] = k4[tid + r * 256];
        }
        __syncthreads();
        #pragma unroll 4
        for (int p = p0; p < p0 + 32; p++) {
            float4 qv = *(const float4*)(qS + p * 32 + i0);
            ulonglong2 kv = *(const ulonglong2*)(kS + p * 32 + j0);
            u64t qp[4];
            PACK2(qp[0], qv.x); PACK2(qp[1], qv.y);
            PACK2(qp[2], qv.z); PACK2(qp[3], qv.w);
            #pragma unroll
            for (int a = 0; a < 4; a++) {
                FFMA2(acc2[a][0], qp[a], kv.x, acc2[a][0]);
                FFMA2(acc2[a][1], qp[a], kv.y, acc2[a][1]);
            }
        }
        __syncthreads();
    }

    #pragma unroll
    for (int a = 0; a < 4; a++) {
        unsigned v0, v1, v2, v3;
        UNPACK2(v0, v1, acc2[a][0]);
        UNPACK2(v2, v3, acc2[a][1]);
        *(float4*)(red + g * 1024 + (i0 + a) * 32 + j0) =
            make_float4(__uint_as_float(v0), __uint_as_float(v1),
                        __uint_as_float(v2), __uint_as_float(v3));
    }
    __syncthreads();

    float4 r0 = ((const float4*)(red))[tid];
    float4 r1 = ((const float4*)(red + 1024))[tid];
    float4 r2 = ((const float4*)(red + 2048))[tid];
    float4 r3 = ((const float4*)(red + 3072))[tid];
    float4 o = make_float4(r0.x + r1.x + r2.x + r3.x,
                           r0.y + r1.y + r2.y + r3.y,
                           r0.z + r1.z + r2.z + r3.z,
                           r0.w + r1.w + r2.w + r3.w);
    float* dst = g_lpart + (size_t)((b * NHK + n) * 8 + s) * 1024;
    ((float4*)dst)[tid] = o;
}

// ---------------------------------------------------------------------------
// K3b: reduce partials + scale + ALiBi + mask + softmax. grid=(NH,B), 1024thr.
// ---------------------------------------------------------------------------
__global__ void k3b_softmax() {
    int n = blockIdx.x, b = blockIdx.y;
    int tid = threadIdx.x;
    int i = tid >> 5, j = tid & 31;
    float slope = exp2f(-(float)(n + 1));
    const float* src = g_lpart + (size_t)(b * NHK + n) * 8 * TT * TT + i * 32 + j;
    float v = 0.f;
    #pragma unroll
    for (int s = 0; s < 8; s++) v += src[s * 1024];
    v = v * SCALE_LOGIT + slope * (-fabsf((float)(i - j)));
    if (j <= i) v = -1e18f;   // faithful: lower triangle masked
    float mx = v;
    #pragma unroll
    for (int d = 16; d > 0; d >>= 1) mx = fmaxf(mx, __shfl_xor_sync(0xffffffffu, mx, d));
    float e = expf(v - mx);
    float sum = e;
    #pragma unroll
    for (int d = 16; d > 0; d >>= 1) sum += __shfl_xor_sync(0xffffffffu, sum, d);
    g_attn[(size_t)(b * NHK + n) * TT * TT + i * 32 + j] = e / sum;
}

// ---------------------------------------------------------------------------
// K4a: tmp[c, hw, t] = sum_j v[c, hw, j] * attn[n(c)][t][j]
// grid=(8 hwTiles, 64 c, B), 256 thr.
// ---------------------------------------------------------------------------
#define APS 34
__global__ void k4a_av() {
    __shared__ __align__(16) float attnS[TT * APS];    // [t][j]
    __shared__ __align__(16) float sV[128 * APS];      // [hw][j]

    int hwt = blockIdx.x, c = blockIdx.y, b = blockIdx.z;
    int n = c >> 3;
    int tid = threadIdx.x;

    {
        const float* a = g_attn + (size_t)(b * NHK + n) * TT * TT;
        #pragma unroll
        for (int k = 0; k < 4; k++) {
            int idx = tid + k * 256;
            attnS[(idx >> 5) * APS + (idx & 31)] = a[idx];
        }
    }
    {
        const ulonglong2* v2 = (const ulonglong2*)(g_qkv + ((size_t)(b * QKVO + 128 + c) * COLS) + hwt * 128 * TT);
        u64t* sVu = (u64t*)sV;
        #pragma unroll
        for (int k = 0; k < 4; k++) {
            int idx = tid + k * 256;
            int hw = idx >> 3, j4 = idx & 7;
            ulonglong2 val = v2[idx];
            sVu[hw * (APS / 2) + j4 * 2]     = val.x;
            sVu[hw * (APS / 2) + j4 * 2 + 1] = val.y;
        }
    }
    __syncthreads();

    int tx = tid & 31, ty = tid >> 5;
    int t0 = ty * 4;
    const u64t* aU = (const u64t*)attnS;
    const u64t* vU = (const u64t*)sV;

    u64t acc2[4][4];
    #pragma unroll
    for (int i = 0; i < 4; i++)
        #pragma unroll
        for (int t = 0; t < 4; t++) acc2[i][t] = 0ull;

    #pragma unroll 8
    for (int j2 = 0; j2 < 16; j2++) {
        u64t av[4], vv[4];
        #pragma unroll
        for (int t = 0; t < 4; t++) av[t] = aU[(t0 + t) * (APS / 2) + j2];
        #pragma unroll
        for (int i = 0; i < 4; i++) vv[i] = vU[(tx + 32 * i) * (APS / 2) + j2];
        #pragma unroll
        for (int i = 0; i < 4; i++)
            #pragma unroll
            for (int t = 0; t < 4; t++)
                FFMA2(acc2[i][t], vv[i], av[t], acc2[i][t]);
    }

    float* dst = g_tmp + (size_t)(b * CC_ + c) * COLS + hwt * 128 * TT;
    #pragma unroll
    for (int i = 0; i < 4; i++) {
        float r[4];
        #pragma unroll
        for (int t = 0; t < 4; t++) {
            unsigned lo, hi;
            UNPACK2(lo, hi, acc2[i][t]);
            r[t] = __uint_as_float(lo) + __uint_as_float(hi);
        }
        *(float4*)(dst + (tx + 32 * i) * TT + t0) = make_float4(r[0], r[1], r[2], r[3]);
    }
}

// ---------------------------------------------------------------------------
// K4b: out = Wp(64x64) @ tmp(64x32768) per batch + proj noise/bias.
// grid=(256,1,B), 256 thr.
// ---------------------------------------------------------------------------
__global__ void k4b_proj(const float* __restrict__ proj_np,
                         const float* __restrict__ proj_bp,
                         const float* __restrict__ proj_noise,
                         float* __restrict__ out) {
    extern __shared__ float smem[];
    float* sX = smem;            // [64][128]
    float* sW = smem + 64 * 128; // [c][o]

    int b = blockIdx.z, nb = blockIdx.x;
    int tid = threadIdx.x;
    int colBase = nb * 128;

    const float4* xs = (const float4*)(g_tmp + (size_t)b * (CC_ * COLS) + colBase);
    #pragma unroll
    for (int i = 0; i < 8; i++) {
        int fidx = tid + i * 256;
        int r = fidx >> 5, c4 = fidx & 31;
        ((float4*)sX)[r * 32 + c4] = xs[r * (COLS / 4) + c4];
    }
    const float* gw = g_wproj + b * CC_ * CC_;
    #pragma unroll
    for (int i = 0; i < 16; i++) {
        int fidx = tid + i * 256;
        int ol = fidx >> 6, c = fidx & 63;
        sW[c * 64 + ol] = gw[ol * CC_ + c];
    }
    __syncthreads();

    int tx = tid & 15, ty = tid >> 4;
    u64t acc2[4][4];
    #pragma unroll
    for (int oi = 0; oi < 4; oi++)
        #pragma unroll
        for (int p = 0; p < 4; p++) acc2[oi][p] = 0ull;

    #pragma unroll 8
    for (int c = 0; c < 64; c++) {
        float4 w4 = *(const float4*)(sW + c * 64 + ty * 4);
        u64t wp[4];
        PACK2(wp[0], w4.x); PACK2(wp[1], w4.y);
        PACK2(wp[2], w4.z); PACK2(wp[3], w4.w);
        ulonglong2 xa = *(const ulonglong2*)(sX + c * 128 + tx * 4);
        ulonglong2 xb = *(const ulonglong2*)(sX + c * 128 + 64 + tx * 4);
        #pragma unroll
        for (int oi = 0; oi < 4; oi++) {
            FFMA2(acc2[oi][0], wp[oi], xa.x, acc2[oi][0]);
            FFMA2(acc2[oi][1], wp[oi], xa.y, acc2[oi][1]);
            FFMA2(acc2[oi][2], wp[oi], xb.x, acc2[oi][2]);
            FFMA2(acc2[oi][3], wp[oi], xb.y, acc2[oi][3]);
        }
    }

    int colA = colBase + tx * 4;
    int colB = colA + 64;
    float4 nzA = *(const float4*)(proj_noise + b * COLS + colA);
    float4 nzB = *(const float4*)(proj_noise + b * COLS + colB);
    #pragma unroll
    for (int oi = 0; oi < 4; oi++) {
        int o = ty * 4 + oi;
        float npc = proj_np[o], bpc = proj_bp[o];
        unsigned r0, r1, r2, r3;
        float* dst = out + (size_t)(b * CC_ + o) * COLS;
        UNPACK2(r0, r1, acc2[oi][0]);
        UNPACK2(r2, r3, acc2[oi][1]);
        *(float4*)(dst + colA) = make_float4(
            __uint_as_float(r0) + npc * nzA.x + bpc,
            __uint_as_float(r1) + npc * nzA.y + bpc,
            __uint_as_float(r2) + npc * nzA.z + bpc,
            __uint_as_float(r3) + npc * nzA.w + bpc);
        UNPACK2(r0, r1, acc2[oi][2]);
        UNPACK2(r2, r3, acc2[oi][3]);
        *(float4*)(dst + colB) = make_float4(
            __uint_as_float(r0) + npc * nzB.x + bpc,
            __uint_as_float(r1) + npc * nzB.y + bpc,
            __uint_as_float(r2) + npc * nzB.z + bpc,
            __uint_as_float(r3) + npc * nzB.w + bpc);
    }
}

// ---------------------------------------------------------------------------
extern "C" void kernel_launch(void* const* d_in, const int* in_sizes, int n_in,
                              void* d_out, int out_size) {
    const float* x          = (const float*)d_in[0];
    const float* style      = (const float*)d_in[1];
    const float* qkv_w      = (const float*)d_in[2];
    const float* qkv_lw     = (const float*)d_in[3];
    const float* qkv_lb     = (const float*)d_in[4];
    const float* qkv_np     = (const float*)d_in[5];
    const float* qkv_bp     = (const float*)d_in[6];
    const float* qkv_noise  = (const float*)d_in[7];
    const float* proj_w     = (const float*)d_in[8];
    const float* proj_lw    = (const float*)d_in[9];
    const float* proj_lb    = (const float*)d_in[10];
    const float* proj_np    = (const float*)d_in[11];
    const float* proj_bp    = (const float*)d_in[12];
    const float* proj_noise = (const float*)d_in[13];
    float* out = (float*)d_out;

    const int smem_k2   = (64 * 128 + 3 * 64 * 64) * 4;   // 81920
    const int smem_gemm = (64 * 128 + 64 * 64) * 4;       // 49152
    cudaFuncSetAttribute(k2_qkv,   cudaFuncAttributeMaxDynamicSharedMemorySize, smem_k2);
    cudaFuncSetAttribute(k4b_proj, cudaFuncAttributeMaxDynamicSharedMemorySize, smem_gemm);

    k1_weights<<<BB, 256>>>(style, qkv_w, qkv_lw, qkv_lb, proj_w, proj_lw, proj_lb);
    k2_qkv<<<dim3(256, BB), 256, smem_k2>>>(x, qkv_np, qkv_bp, qkv_noise);
    k3a_logits<<<dim3(8, NHK, BB), 256>>>();
    k3b_softmax<<<dim3(NHK, BB), 1024>>>();
    k4a_av<<<dim3(8, CC_, BB), 256>>>();
    k4b_proj<<<dim3(256, 1, BB), 256, smem_gemm>>>(proj_np, proj_bp, proj_noise, out);
}